// round 13
// baseline (speedup 1.0000x reference)
#include <cuda_runtime.h>
#include <math.h>

// Problem constants: N=8, R=256, IN=64, OUT=64, MODE=32
// kx mode list (64): k<32 -> kx=k ; k>=32 -> kx=192+k

// ---------------- device scratch ----------------
__device__ float g_TA[128 * 64];      // fwd w-DFT folded: [w][r]  r<32: cos(2pi ky w/256), r>=32: -sin
__device__ float g_TB[128 * 128];     // fwd h-DFT folded: [h][c]  c<64: cos(2pi kx h/256), c>=64: +sin
__device__ float g_T4T[128 * 512];    // inv h-DFT, transposed: [kxp][hp]
__device__ float g_T5t[64 * 256];     // inv w-DFT, transposed: [kyp][w]
__device__ float g_Xw[(size_t)8 * 256 * 4096];  // [n][h][p*2048+ky*64+i]  (33.5MB)
__device__ float g_C [(size_t)8 * 128 * 4096];  // [n][m(cos|sin)][p*2048+ky*64+i] (16.8MB)
__device__ float g_F [(size_t)8 * 128 * 32 * 64]; // [n][kxp][ky][o] (8.4MB)
__device__ float g_G [(size_t)8 * 512 * 2048];    // [n][hp][ky*64+o] (33.5MB)

__device__ __forceinline__ float silu_f(float t) {
    return t / (1.0f + __expf(-t));
}

// ---------------- twiddle init ----------------
__global__ void k_init() {
    int t = blockIdx.x * blockDim.x + threadIdx.x;   // 16384 threads
    if (t < 8192) {
        // g_TA[w][r]: r<32: cos(2pi ky w/256); r>=32: -sin
        int w = t >> 6, rr = t & 63;
        int ty = rr >> 5, ky = rr & 31;
        float s, c;
        sincospif((float)((ky * w) & 255) * (1.0f / 128.0f), &s, &c);
        g_TA[w * 64 + rr] = ty ? -s : c;
    }
    {
        // g_TB[h][c]: c<64: cos(2pi kx h/256); c>=64: +sin
        int h = t >> 7, cc = t & 127;
        int ty = cc >> 6, k = cc & 63;
        int kx = (k < 32) ? k : 192 + k;
        float s, c;
        sincospif((float)((kx * h) & 255) * (1.0f / 128.0f), &s, &c);
        g_TB[h * 128 + cc] = ty ? s : c;
    }
    {
        // T4T[kxp][hp]: inverse e^{+i2pi kx h/256}
        int h = t >> 6, k = t & 63;
        int kx = (k < 32) ? k : 192 + k;
        float s, c;
        sincospif((float)((kx * h) & 255) * (1.0f / 128.0f), &s, &c);
        g_T4T[(2 * k)     * 512 + 2 * h]     = c;
        g_T4T[(2 * k + 1) * 512 + 2 * h]     = -s;
        g_T4T[(2 * k)     * 512 + 2 * h + 1] = s;
        g_T4T[(2 * k + 1) * 512 + 2 * h + 1] = c;
    }
    {
        // T5t[kyp][w]: y[w] = sum_ky c_ky*(Gre*cos - Gim*sin), c_0=1 else 2
        int r = t >> 8, w = t & 255;
        int ky = r >> 1, p = r & 1;
        float s, c;
        sincospif((float)((ky * w) & 255) * (1.0f / 128.0f), &s, &c);
        float f = (ky == 0) ? 1.0f : 2.0f;
        g_T5t[r * 256 + w] = p ? -f * s : f * c;
    }
}

// ---------------- Stage A (folded): per (n, 8h, type t) ----------------
__global__ void __launch_bounds__(256) k_a(const float* __restrict__ x) {
    __shared__ float As[16][36];     // [kk][32 r]
    __shared__ float Bs[16][512];    // [kk][8h x 64i]
    __shared__ float xs[512];        // x[*, w=128, *] for correction (t=0)
    int tid = threadIdx.x;
    int hg = blockIdx.x, t = blockIdx.y, n = blockIdx.z;
    int h0 = hg * 8;
    const float* xb = x + (size_t)n * 4194304 + (size_t)h0 * 16384;
    if (tid < 128) {
        int hl = tid >> 4, i4 = tid & 15;
        *(float4*)&xs[hl * 64 + i4 * 4] = *(const float4*)(xb + hl * 16384 + 128 * 64 + i4 * 4);
    }
    float acc[4][16] = {};
    int r0 = (tid >> 5) * 4;
    int cg0 = (tid & 31) * 4;        // 4 strided f4 col groups: cg0 + g*128

    for (int kc = 0; kc < 128; kc += 16) {
        if (tid < 128) {
            int kk = tid >> 3, r4 = tid & 7;
            *(float4*)&As[kk][r4 * 4] = *(const float4*)(g_TA + (kc + kk) * 64 + t * 32 + r4 * 4);
        }
#pragma unroll
        for (int q = 0; q < 8; q++) {
            int e = tid + q * 256;
            int kk = e >> 7, c4 = e & 127;
            int hl = c4 >> 4, i4 = c4 & 15;
            int w = kc + kk;
            int m = (256 - w) & 255;
            const float* base = xb + hl * 16384;
            float4 vw = *(const float4*)(base + (size_t)w * 64 + i4 * 4);
            float4 vm = *(const float4*)(base + (size_t)m * 64 + i4 * 4);
            float4 v;
            if (t == 0) {
                v = w ? make_float4(vw.x + vm.x, vw.y + vm.y, vw.z + vm.z, vw.w + vm.w) : vw;
            } else {
                v = w ? make_float4(vw.x - vm.x, vw.y - vm.y, vw.z - vm.z, vw.w - vm.w)
                      : make_float4(0.f, 0.f, 0.f, 0.f);
            }
            *(float4*)&Bs[kk][c4 * 4] = v;
        }
        __syncthreads();
#pragma unroll
        for (int k = 0; k < 16; k++) {
            float a[4], b[16];
            *(float4*)a = *(float4*)&As[k][r0];
#pragma unroll
            for (int g = 0; g < 4; g++)
                *(float4*)(b + g * 4) = *(float4*)&Bs[k][cg0 + g * 128];
#pragma unroll
            for (int i = 0; i < 4; i++)
#pragma unroll
                for (int j = 0; j < 16; j++) acc[i][j] += a[i] * b[j];
        }
        __syncthreads();
    }
    if (t == 0) {
#pragma unroll
        for (int r = 0; r < 4; r++) {
            float sign = ((r0 + r) & 1) ? -1.0f : 1.0f;
#pragma unroll
            for (int g = 0; g < 4; g++) {
                int cg = cg0 + g * 128;
#pragma unroll
                for (int j = 0; j < 4; j++) acc[r][g * 4 + j] += sign * xs[cg + j];
            }
        }
    }
#pragma unroll
    for (int r = 0; r < 4; r++) {
        int ky = r0 + r;
#pragma unroll
        for (int g = 0; g < 4; g++) {
            int cg = cg0 + g * 128;
            int hl = cg >> 6, ib = cg & 63;
            float* O = g_Xw + (size_t)n * 1048576 + (size_t)(h0 + hl) * 4096 + t * 2048 + ky * 64 + ib;
            *(float4*)O = make_float4(acc[r][g * 4 + 0], acc[r][g * 4 + 1],
                                      acc[r][g * 4 + 2], acc[r][g * 4 + 3]);
        }
    }
}

// ---------------- Stage B (folded): per (colblock, n, type t) ----------------
__global__ void __launch_bounds__(256, 2) k_b() {
    __shared__ float As[2][16][68];   // [kk][64 k]
    __shared__ float Bs[2][16][128];
    __shared__ float xs[128];         // Xw[n][128][cols] for correction
    int tid = threadIdx.x;
    int cb = blockIdx.x * 128;
    int n = blockIdx.y, t = blockIdx.z;
    const float* B = g_Xw + (size_t)n * 1048576;
    if (tid < 32)
        *(float4*)&xs[tid * 4] = *(const float4*)(B + (size_t)128 * 4096 + cb + tid * 4);
    float acc[8][4] = {};
    int r0 = (tid >> 5) * 8, c0 = (tid & 31) * 4;
    int ka = tid >> 4, ra4 = tid & 15;

    float4 pa;
    float4 ph[2], pm[2];
    pa = *(const float4*)(g_TB + ka * 128 + t * 64 + ra4 * 4);
#pragma unroll
    for (int q = 0; q < 2; q++) {
        int e = tid + q * 256;
        int kk = e >> 5, c4 = e & 31;
        int m = (256 - kk) & 255;
        ph[q] = *(const float4*)(B + (size_t)kk * 4096 + cb + c4 * 4);
        pm[q] = *(const float4*)(B + (size_t)m * 4096 + cb + c4 * 4);
    }
    {
        *(float4*)&As[0][ka][ra4 * 4] = pa;
#pragma unroll
        for (int q = 0; q < 2; q++) {
            int e = tid + q * 256;
            int kk = e >> 5, c4 = e & 31;
            float4 v;
            if (t == 0)
                v = kk ? make_float4(ph[q].x + pm[q].x, ph[q].y + pm[q].y,
                                     ph[q].z + pm[q].z, ph[q].w + pm[q].w) : ph[q];
            else
                v = kk ? make_float4(ph[q].x - pm[q].x, ph[q].y - pm[q].y,
                                     ph[q].z - pm[q].z, ph[q].w - pm[q].w)
                       : make_float4(0.f, 0.f, 0.f, 0.f);
            *(float4*)&Bs[0][kk][c4 * 4] = v;
        }
    }
    __syncthreads();
    int buf = 0;
    for (int kc = 0; kc < 128; kc += 16) {
        if (kc + 16 < 128) {
            pa = *(const float4*)(g_TB + (kc + 16 + ka) * 128 + t * 64 + ra4 * 4);
#pragma unroll
            for (int q = 0; q < 2; q++) {
                int e = tid + q * 256;
                int kk = e >> 5, c4 = e & 31;
                int h = kc + 16 + kk;
                int m = (256 - h) & 255;
                ph[q] = *(const float4*)(B + (size_t)h * 4096 + cb + c4 * 4);
                pm[q] = *(const float4*)(B + (size_t)m * 4096 + cb + c4 * 4);
            }
        }
#pragma unroll
        for (int k = 0; k < 16; k++) {
            float a[8], b[4];
            *(float4*)(a)     = *(float4*)&As[buf][k][r0];
            *(float4*)(a + 4) = *(float4*)&As[buf][k][r0 + 4];
            *(float4*)(b)     = *(float4*)&Bs[buf][k][c0];
#pragma unroll
            for (int i = 0; i < 8; i++)
#pragma unroll
                for (int j = 0; j < 4; j++) acc[i][j] += a[i] * b[j];
        }
        if (kc + 16 < 128) {
            *(float4*)&As[buf ^ 1][ka][ra4 * 4] = pa;
#pragma unroll
            for (int q = 0; q < 2; q++) {
                int e = tid + q * 256;
                int kk = e >> 5, c4 = e & 31;
                float4 v;
                if (t == 0)
                    v = make_float4(ph[q].x + pm[q].x, ph[q].y + pm[q].y,
                                    ph[q].z + pm[q].z, ph[q].w + pm[q].w);
                else
                    v = make_float4(ph[q].x - pm[q].x, ph[q].y - pm[q].y,
                                    ph[q].z - pm[q].z, ph[q].w - pm[q].w);
                *(float4*)&Bs[buf ^ 1][kk][c4 * 4] = v;
            }
        }
        __syncthreads();
        buf ^= 1;
    }
    if (t == 0) {
#pragma unroll
        for (int r = 0; r < 8; r++) {
            float sign = ((r0 + r) & 1) ? -1.0f : 1.0f;
#pragma unroll
            for (int j = 0; j < 4; j++) acc[r][j] += sign * xs[c0 + j];
        }
    }
    float* C = g_C + (size_t)n * 524288 + (size_t)(t * 64) * 4096 + cb;
#pragma unroll
    for (int i = 0; i < 8; i++) {
        int row = r0 + i;
        *(float4*)(C + (size_t)row * 4096 + c0) =
            make_float4(acc[i][0], acc[i][1], acc[i][2], acc[i][3]);
    }
}

// ---------------- S3: complex recombine + mode channel mix, scale 1/65536 ----------------
__global__ void __launch_bounds__(256) k_c(const float* __restrict__ w0,
                                           const float* __restrict__ w1) {
    __shared__ float Wre[64][64], Wim[64][64];
    __shared__ float Xre[8][64], Xim[8][64];
    int tid = threadIdx.x;
    int ky = blockIdx.x & 31, k = blockIdx.x >> 5;
    const float* W = (k < 32) ? (w0 + (size_t)(k * 32 + ky) * 4096 * 2)
                              : (w1 + (size_t)((k - 32) * 32 + ky) * 4096 * 2);
#pragma unroll
    for (int q = 0; q < 16; q++) {
        int e = tid + q * 256;          // i*64+o
        float2 v = *(const float2*)(W + (size_t)e * 2);
        Wre[e >> 6][e & 63] = v.x;
        Wim[e >> 6][e & 63] = v.y;
    }
#pragma unroll
    for (int q = 0; q < 2; q++) {
        int e = tid + q * 256;          // n*64+i
        int n = e >> 6, i = e & 63;
        const float* Cn = g_C + (size_t)n * 524288;
        float cc0 = Cn[(size_t)k * 4096 + ky * 64 + i];
        float cc1 = Cn[(size_t)k * 4096 + 2048 + ky * 64 + i];
        float cs0 = Cn[(size_t)(64 + k) * 4096 + ky * 64 + i];
        float cs1 = Cn[(size_t)(64 + k) * 4096 + 2048 + ky * 64 + i];
        Xre[n][i] = cc0 + cs1;
        Xim[n][i] = cc1 - cs0;
    }
    __syncthreads();
    const float sc = 1.0f / 65536.0f;
#pragma unroll
    for (int q = 0; q < 2; q++) {
        int e = tid + q * 256;
        int n = e >> 6, o = e & 63;
        float fre = 0.0f, fim = 0.0f;
#pragma unroll 8
        for (int i = 0; i < 64; i++) {
            float xr = Xre[n][i], xi = Xim[n][i];
            float wr = Wre[i][o], wi = Wim[i][o];
            fre += xr * wr - xi * wi;
            fim += xr * wi + xi * wr;
        }
        g_F[((size_t)(n * 128 + 2 * k) * 32 + ky) * 64 + o]     = fre * sc;
        g_F[((size_t)(n * 128 + 2 * k + 1) * 32 + ky) * 64 + o] = fim * sc;
    }
}

// ---------------- S4: per n: G[512 hp][2048] = T4[512][128] @ F[n], double-buffered ----------------
__global__ void __launch_bounds__(256, 2) k_s4() {
    __shared__ float As[2][16][132];
    __shared__ float Bs[2][16][128];
    int tid = threadIdx.x;
    int colbase = blockIdx.x * 128;
    int m0 = blockIdx.y * 128;
    int n = blockIdx.z;
    const float* B = g_F + (size_t)n * 128 * 2048;
    float acc[8][8] = {};
    int r0 = (tid >> 4) * 8, c0 = (tid & 15) * 8;

    float4 pa[2], pb[2];
#pragma unroll
    for (int q = 0; q < 2; q++) {
        int e = tid + q * 256;
        int kk = e >> 5, m4 = e & 31;
        pa[q] = *(const float4*)(g_T4T + (size_t)kk * 512 + m0 + m4 * 4);
        pb[q] = *(const float4*)(B + (size_t)kk * 2048 + colbase + m4 * 4);
    }
#pragma unroll
    for (int q = 0; q < 2; q++) {
        int e = tid + q * 256;
        int kk = e >> 5, m4 = e & 31;
        *(float4*)&As[0][kk][m4 * 4] = pa[q];
        *(float4*)&Bs[0][kk][m4 * 4] = pb[q];
    }
    __syncthreads();
    int buf = 0;
    for (int kc = 0; kc < 128; kc += 16) {
        if (kc + 16 < 128) {
#pragma unroll
            for (int q = 0; q < 2; q++) {
                int e = tid + q * 256;
                int kk = e >> 5, m4 = e & 31;
                pa[q] = *(const float4*)(g_T4T + (size_t)(kc + 16 + kk) * 512 + m0 + m4 * 4);
                pb[q] = *(const float4*)(B + (size_t)(kc + 16 + kk) * 2048 + colbase + m4 * 4);
            }
        }
#pragma unroll
        for (int k = 0; k < 16; k++) {
            float a[8], b[8];
            *(float4*)(a)     = *(float4*)&As[buf][k][r0];
            *(float4*)(a + 4) = *(float4*)&As[buf][k][r0 + 4];
            *(float4*)(b)     = *(float4*)&Bs[buf][k][c0];
            *(float4*)(b + 4) = *(float4*)&Bs[buf][k][c0 + 4];
#pragma unroll
            for (int i = 0; i < 8; i++)
#pragma unroll
                for (int j = 0; j < 8; j++) acc[i][j] += a[i] * b[j];
        }
        if (kc + 16 < 128) {
#pragma unroll
            for (int q = 0; q < 2; q++) {
                int e = tid + q * 256;
                int kk = e >> 5, m4 = e & 31;
                *(float4*)&As[buf ^ 1][kk][m4 * 4] = pa[q];
                *(float4*)&Bs[buf ^ 1][kk][m4 * 4] = pb[q];
            }
        }
        __syncthreads();
        buf ^= 1;
    }
    float* C = g_G + (size_t)n * 512 * 2048 + colbase;
#pragma unroll
    for (int i = 0; i < 8; i++) {
        int row = m0 + r0 + i;
        *(float4*)(C + (size_t)row * 2048 + c0)     = make_float4(acc[i][0], acc[i][1], acc[i][2], acc[i][3]);
        *(float4*)(C + (size_t)row * 2048 + c0 + 4) = make_float4(acc[i][4], acc[i][5], acc[i][6], acc[i][7]);
    }
}

// ---------------- S5 (folded inverse w-DFT + fused residual): per (n,h).
// Spectral: E[w]=Σ T5t[2ky][w]·Gre, O[w]=Σ T5t[2ky+1][w]·Gim for w=0..127.
// y[w]=E+O, y[256-w]=E-O (w>=1); y[128] special; y[0]=E[0] (O[0]=0).
// Residual: two sub-passes accumulate into both banks. Then +bias, silu. ----------------
__global__ void __launch_bounds__(256, 2) k_s5(const float* __restrict__ x,
                                               const float* __restrict__ rw,
                                               const float* __restrict__ rb,
                                               float* __restrict__ out) {
    extern __shared__ float sm[];
    float(*As)[132] = (float(*)[132])sm;              // [64 k][128 w(+pad)]
    float(*Bs)[68]  = (float(*)[68])(sm + 64 * 132);  // [64 k][64 o(+pad)]
    float* bb = sm + 64 * 132 + 64 * 68;
    int tid = threadIdx.x;
    int h = blockIdx.x & 255, n = blockIdx.x >> 8;
    int r0 = (tid >> 3) * 4;          // 32 row-groups x 4 = 128 w rows
    int c0 = (tid & 7) * 8;           // 8 col-groups x 8 = 64 o cols
    float accE[4][8] = {};            // -> yp = y[w]
    float accO[4][8] = {};            // -> ym = y[mirror]

    // ----- pass 1 fill: As = T5t[kyp][w 0..127], Bs = G[kyp][o], bb = rb -----
#pragma unroll
    for (int q = 0; q < 8; q++) {
        int e = tid + q * 256;           // 2048 f4 : 64 k x 32 w4
        int k = e >> 5, w4 = e & 31;
        *(float4*)&As[k][w4 * 4] = *(const float4*)(g_T5t + k * 256 + w4 * 4);
    }
    const float* G = g_G + (size_t)(n * 256 + h) * 4096;  // [p][ky][o]
#pragma unroll
    for (int q = 0; q < 4; q++) {
        int e4 = tid + q * 256;          // 1024 f4
        int p = e4 >> 9, ky = (e4 >> 4) & 31, j = e4 & 15;
        float4 v = *(const float4*)(G + p * 2048 + ky * 64 + j * 4);
        *(float4*)&Bs[2 * ky + p][j * 4] = v;
    }
    if (tid < 64) bb[tid] = rb[tid];
    __syncthreads();

    // ----- spectral loop: E from even rows (Gre), O from odd rows (Gim) -----
#pragma unroll 4
    for (int ky = 0; ky < 32; ky++) {
        float aE[4], bE[8], aO[4], bO[8];
        *(float4*)aE       = *(float4*)&As[2 * ky][r0];
        *(float4*)(bE)     = *(float4*)&Bs[2 * ky][c0];
        *(float4*)(bE + 4) = *(float4*)&Bs[2 * ky][c0 + 4];
        *(float4*)aO       = *(float4*)&As[2 * ky + 1][r0];
        *(float4*)(bO)     = *(float4*)&Bs[2 * ky + 1][c0];
        *(float4*)(bO + 4) = *(float4*)&Bs[2 * ky + 1][c0 + 4];
#pragma unroll
        for (int i = 0; i < 4; i++)
#pragma unroll
            for (int j = 0; j < 8; j++) {
                accE[i][j] += aE[i] * bE[j];
                accO[i][j] += aO[i] * bO[j];
            }
    }
    // combine: accE := y[w] = E+O ; accO := y[mirror] = E-O
#pragma unroll
    for (int i = 0; i < 4; i++)
#pragma unroll
        for (int j = 0; j < 8; j++) {
            float e = accE[i][j], o = accO[i][j];
            accE[i][j] = e + o;
            accO[i][j] = e - o;
        }
    // w=0 threads: mirror slot holds y[128] = sum_ky c_ky*(-1)^ky * Gre[ky]
    if (r0 == 0) {
#pragma unroll
        for (int j = 0; j < 8; j++) {
            float s = 0.0f;
#pragma unroll
            for (int ky = 0; ky < 32; ky++) {
                float sgn = (ky == 0) ? 1.0f : ((ky & 1) ? -2.0f : 2.0f);
                s += sgn * Bs[2 * ky][c0 + j];
            }
            accO[0][j] = s;
        }
    }
    __syncthreads();

    // ----- pass 2a: residual for w 0..127 into accE -----
    const float* xb = x + (size_t)(n * 256 + h) * 16384;   // [w][i]
#pragma unroll
    for (int q = 0; q < 8; q++) {
        int f4 = tid + q * 256;          // 2048 f4 : 128 w x 16 i4
        int w = f4 >> 4, j = f4 & 15;
        float4 v = *(const float4*)(xb + w * 64 + j * 4);
        As[j * 4 + 0][w] = v.x; As[j * 4 + 1][w] = v.y;
        As[j * 4 + 2][w] = v.z; As[j * 4 + 3][w] = v.w;
    }
#pragma unroll
    for (int q = 0; q < 4; q++) {
        int f4 = tid + q * 256;          // 1024 f4 : 64 k x 16 j
        int k = f4 >> 4, j = f4 & 15;
        *(float4*)&Bs[k][j * 4] = *(const float4*)(rw + k * 64 + j * 4);
    }
    __syncthreads();
#pragma unroll 8
    for (int k = 0; k < 64; k++) {
        float a[4], b[8];
        *(float4*)a       = *(float4*)&As[k][r0];
        *(float4*)(b)     = *(float4*)&Bs[k][c0];
        *(float4*)(b + 4) = *(float4*)&Bs[k][c0 + 4];
#pragma unroll
        for (int i = 0; i < 4; i++)
#pragma unroll
            for (int j = 0; j < 8; j++) accE[i][j] += a[i] * b[j];
    }
    __syncthreads();

    // ----- pass 2b: residual for mirror rows into accO.
    // Fill As column jc such that As[*][jc] = x[wm][*] with wm=(jc==0)?128:256-jc.
    // Source rows w=128..255: target jc = (w==128)?0:256-w = (128 - (w-128)) & 127.
#pragma unroll
    for (int q = 0; q < 8; q++) {
        int f4 = tid + q * 256;
        int wl = f4 >> 4, j = f4 & 15;   // source row 128+wl
        int jc = (128 - wl) & 127;
        float4 v = *(const float4*)(xb + (size_t)(128 + wl) * 64 + j * 4);
        As[j * 4 + 0][jc] = v.x; As[j * 4 + 1][jc] = v.y;
        As[j * 4 + 2][jc] = v.z; As[j * 4 + 3][jc] = v.w;
    }
    __syncthreads();
#pragma unroll 8
    for (int k = 0; k < 64; k++) {
        float a[4], b[8];
        *(float4*)a       = *(float4*)&As[k][r0];
        *(float4*)(b)     = *(float4*)&Bs[k][c0];
        *(float4*)(b + 4) = *(float4*)&Bs[k][c0 + 4];
#pragma unroll
        for (int i = 0; i < 4; i++)
#pragma unroll
            for (int j = 0; j < 8; j++) accO[i][j] += a[i] * b[j];
    }

    // ----- epilogue: bias + silu, write both banks -----
    float* ob = out + (size_t)(n * 256 + h) * 16384;   // [w][o]
#pragma unroll
    for (int i = 0; i < 4; i++) {
        int w = r0 + i;
        int wm = (w == 0) ? 128 : 256 - w;
        float4 p0, p1, m0v, m1v;
        p0.x = silu_f(accE[i][0] + bb[c0 + 0]); p0.y = silu_f(accE[i][1] + bb[c0 + 1]);
        p0.z = silu_f(accE[i][2] + bb[c0 + 2]); p0.w = silu_f(accE[i][3] + bb[c0 + 3]);
        p1.x = silu_f(accE[i][4] + bb[c0 + 4]); p1.y = silu_f(accE[i][5] + bb[c0 + 5]);
        p1.z = silu_f(accE[i][6] + bb[c0 + 6]); p1.w = silu_f(accE[i][7] + bb[c0 + 7]);
        m0v.x = silu_f(accO[i][0] + bb[c0 + 0]); m0v.y = silu_f(accO[i][1] + bb[c0 + 1]);
        m0v.z = silu_f(accO[i][2] + bb[c0 + 2]); m0v.w = silu_f(accO[i][3] + bb[c0 + 3]);
        m1v.x = silu_f(accO[i][4] + bb[c0 + 4]); m1v.y = silu_f(accO[i][5] + bb[c0 + 5]);
        m1v.z = silu_f(accO[i][6] + bb[c0 + 6]); m1v.w = silu_f(accO[i][7] + bb[c0 + 7]);
        *(float4*)(ob + (size_t)w * 64 + c0)      = p0;
        *(float4*)(ob + (size_t)w * 64 + c0 + 4)  = p1;
        *(float4*)(ob + (size_t)wm * 64 + c0)     = m0v;
        *(float4*)(ob + (size_t)wm * 64 + c0 + 4) = m1v;
    }
}

// ---------------- launch ----------------
extern "C" void kernel_launch(void* const* d_in, const int* in_sizes, int n_in,
                              void* d_out, int out_size) {
    const float* x  = (const float*)d_in[0];
    const float* w0 = (const float*)d_in[1];
    const float* w1 = (const float*)d_in[2];
    const float* rw = (const float*)d_in[3];
    const float* rb = (const float*)d_in[4];
    float* out = (float*)d_out;

    const int SMEM_S5 = (64 * 132 + 64 * 68 + 64) * 4;   // 51456 bytes
    cudaFuncSetAttribute(k_s5, cudaFuncAttributeMaxDynamicSharedMemorySize, SMEM_S5);

    k_init<<<64, 256>>>();
    dim3 ga(32, 2, 8);                 // hg, type, n
    k_a<<<ga, 256>>>(x);
    dim3 gb(32, 8, 2);                 // colblock, n, type
    k_b<<<gb, 256>>>();
    k_c<<<2048, 256>>>(w0, w1);
    dim3 g4(16, 4, 8);
    k_s4<<<g4, 256>>>();
    k_s5<<<2048, 256, SMEM_S5>>>(x, rw, rb, out);   // 8 n * 256 h
}

// round 14
// speedup vs baseline: 1.1556x; 1.1556x over previous
#include <cuda_runtime.h>
#include <math.h>

typedef unsigned long long u64;

// Problem constants: N=8, R=256, IN=64, OUT=64, MODE=32
// kx mode list (64): k<32 -> kx=k ; k>=32 -> kx=192+k

// ---------------- device scratch ----------------
__device__ float g_TA[128 * 64];      // fwd w-DFT folded: [w][r]  r<32: cos, r>=32: -sin
__device__ float g_TB[128 * 128];     // fwd h-DFT folded: [h][c]  c<64: cos, c>=64: +sin
__device__ float g_T4T[128 * 512];    // inv h-DFT, transposed: [kxp][hp]
__device__ float g_T5t[64 * 256];     // inv w-DFT, transposed: [kyp][w]
__device__ float g_Xw[(size_t)8 * 256 * 4096];  // [n][h][p*2048+ky*64+i]
__device__ float g_C [(size_t)8 * 128 * 4096];  // [n][m(cos|sin)][p*2048+ky*64+i]
__device__ float g_F [(size_t)8 * 128 * 32 * 64]; // [n][kxp][ky][o]
__device__ float g_G [(size_t)8 * 512 * 2048];    // [n][hp][ky*64+o]

__device__ __forceinline__ float silu_f(float t) {
    return t / (1.0f + __expf(-t));
}

// ---------------- twiddle init ----------------
__global__ void k_init() {
    int t = blockIdx.x * blockDim.x + threadIdx.x;   // 16384 threads
    if (t < 8192) {
        int w = t >> 6, rr = t & 63;
        int ty = rr >> 5, ky = rr & 31;
        float s, c;
        sincospif((float)((ky * w) & 255) * (1.0f / 128.0f), &s, &c);
        g_TA[w * 64 + rr] = ty ? -s : c;
    }
    {
        int h = t >> 7, cc = t & 127;
        int ty = cc >> 6, k = cc & 63;
        int kx = (k < 32) ? k : 192 + k;
        float s, c;
        sincospif((float)((kx * h) & 255) * (1.0f / 128.0f), &s, &c);
        g_TB[h * 128 + cc] = ty ? s : c;
    }
    {
        int h = t >> 6, k = t & 63;
        int kx = (k < 32) ? k : 192 + k;
        float s, c;
        sincospif((float)((kx * h) & 255) * (1.0f / 128.0f), &s, &c);
        g_T4T[(2 * k)     * 512 + 2 * h]     = c;
        g_T4T[(2 * k + 1) * 512 + 2 * h]     = -s;
        g_T4T[(2 * k)     * 512 + 2 * h + 1] = s;
        g_T4T[(2 * k + 1) * 512 + 2 * h + 1] = c;
    }
    {
        int r = t >> 8, w = t & 255;
        int ky = r >> 1, p = r & 1;
        float s, c;
        sincospif((float)((ky * w) & 255) * (1.0f / 128.0f), &s, &c);
        float f = (ky == 0) ? 1.0f : 2.0f;
        g_T5t[r * 256 + w] = p ? -f * s : f * c;
    }
}

// ---------------- Stage A (folded): per (n, 8h, type t) ----------------
__global__ void __launch_bounds__(256) k_a(const float* __restrict__ x) {
    __shared__ float As[16][36];     // [kk][32 r]
    __shared__ float Bs[16][512];    // [kk][8h x 64i]
    __shared__ float xs[512];        // x[*, w=128, *] for correction (t=0)
    int tid = threadIdx.x;
    int hg = blockIdx.x, t = blockIdx.y, n = blockIdx.z;
    int h0 = hg * 8;
    const float* xb = x + (size_t)n * 4194304 + (size_t)h0 * 16384;
    if (tid < 128) {
        int hl = tid >> 4, i4 = tid & 15;
        *(float4*)&xs[hl * 64 + i4 * 4] = *(const float4*)(xb + hl * 16384 + 128 * 64 + i4 * 4);
    }
    float acc[4][16] = {};
    int r0 = (tid >> 5) * 4;
    int cg0 = (tid & 31) * 4;

    for (int kc = 0; kc < 128; kc += 16) {
        if (tid < 128) {
            int kk = tid >> 3, r4 = tid & 7;
            *(float4*)&As[kk][r4 * 4] = *(const float4*)(g_TA + (kc + kk) * 64 + t * 32 + r4 * 4);
        }
#pragma unroll
        for (int q = 0; q < 8; q++) {
            int e = tid + q * 256;
            int kk = e >> 7, c4 = e & 127;
            int hl = c4 >> 4, i4 = c4 & 15;
            int w = kc + kk;
            int m = (256 - w) & 255;
            const float* base = xb + hl * 16384;
            float4 vw = *(const float4*)(base + (size_t)w * 64 + i4 * 4);
            float4 vm = *(const float4*)(base + (size_t)m * 64 + i4 * 4);
            float4 v;
            if (t == 0) {
                v = w ? make_float4(vw.x + vm.x, vw.y + vm.y, vw.z + vm.z, vw.w + vm.w) : vw;
            } else {
                v = w ? make_float4(vw.x - vm.x, vw.y - vm.y, vw.z - vm.z, vw.w - vm.w)
                      : make_float4(0.f, 0.f, 0.f, 0.f);
            }
            *(float4*)&Bs[kk][c4 * 4] = v;
        }
        __syncthreads();
#pragma unroll
        for (int k = 0; k < 16; k++) {
            float a[4], b[16];
            *(float4*)a = *(float4*)&As[k][r0];
#pragma unroll
            for (int g = 0; g < 4; g++)
                *(float4*)(b + g * 4) = *(float4*)&Bs[k][cg0 + g * 128];
#pragma unroll
            for (int i = 0; i < 4; i++)
#pragma unroll
                for (int j = 0; j < 16; j++) acc[i][j] += a[i] * b[j];
        }
        __syncthreads();
    }
    if (t == 0) {
#pragma unroll
        for (int r = 0; r < 4; r++) {
            float sign = ((r0 + r) & 1) ? -1.0f : 1.0f;
#pragma unroll
            for (int g = 0; g < 4; g++) {
                int cg = cg0 + g * 128;
#pragma unroll
                for (int j = 0; j < 4; j++) acc[r][g * 4 + j] += sign * xs[cg + j];
            }
        }
    }
#pragma unroll
    for (int r = 0; r < 4; r++) {
        int ky = r0 + r;
#pragma unroll
        for (int g = 0; g < 4; g++) {
            int cg = cg0 + g * 128;
            int hl = cg >> 6, ib = cg & 63;
            float* O = g_Xw + (size_t)n * 1048576 + (size_t)(h0 + hl) * 4096 + t * 2048 + ky * 64 + ib;
            *(float4*)O = make_float4(acc[r][g * 4 + 0], acc[r][g * 4 + 1],
                                      acc[r][g * 4 + 2], acc[r][g * 4 + 3]);
        }
    }
}

// ---------------- Stage B (folded): per (colblock, n, type t) ----------------
__global__ void __launch_bounds__(256, 2) k_b() {
    __shared__ float As[2][16][68];
    __shared__ float Bs[2][16][128];
    __shared__ float xs[128];
    int tid = threadIdx.x;
    int cb = blockIdx.x * 128;
    int n = blockIdx.y, t = blockIdx.z;
    const float* B = g_Xw + (size_t)n * 1048576;
    if (tid < 32)
        *(float4*)&xs[tid * 4] = *(const float4*)(B + (size_t)128 * 4096 + cb + tid * 4);
    float acc[8][4] = {};
    int r0 = (tid >> 5) * 8, c0 = (tid & 31) * 4;
    int ka = tid >> 4, ra4 = tid & 15;

    float4 pa;
    float4 ph[2], pm[2];
    pa = *(const float4*)(g_TB + ka * 128 + t * 64 + ra4 * 4);
#pragma unroll
    for (int q = 0; q < 2; q++) {
        int e = tid + q * 256;
        int kk = e >> 5, c4 = e & 31;
        int m = (256 - kk) & 255;
        ph[q] = *(const float4*)(B + (size_t)kk * 4096 + cb + c4 * 4);
        pm[q] = *(const float4*)(B + (size_t)m * 4096 + cb + c4 * 4);
    }
    {
        *(float4*)&As[0][ka][ra4 * 4] = pa;
#pragma unroll
        for (int q = 0; q < 2; q++) {
            int e = tid + q * 256;
            int kk = e >> 5, c4 = e & 31;
            float4 v;
            if (t == 0)
                v = kk ? make_float4(ph[q].x + pm[q].x, ph[q].y + pm[q].y,
                                     ph[q].z + pm[q].z, ph[q].w + pm[q].w) : ph[q];
            else
                v = kk ? make_float4(ph[q].x - pm[q].x, ph[q].y - pm[q].y,
                                     ph[q].z - pm[q].z, ph[q].w - pm[q].w)
                       : make_float4(0.f, 0.f, 0.f, 0.f);
            *(float4*)&Bs[0][kk][c4 * 4] = v;
        }
    }
    __syncthreads();
    int buf = 0;
    for (int kc = 0; kc < 128; kc += 16) {
        if (kc + 16 < 128) {
            pa = *(const float4*)(g_TB + (kc + 16 + ka) * 128 + t * 64 + ra4 * 4);
#pragma unroll
            for (int q = 0; q < 2; q++) {
                int e = tid + q * 256;
                int kk = e >> 5, c4 = e & 31;
                int h = kc + 16 + kk;
                int m = (256 - h) & 255;
                ph[q] = *(const float4*)(B + (size_t)h * 4096 + cb + c4 * 4);
                pm[q] = *(const float4*)(B + (size_t)m * 4096 + cb + c4 * 4);
            }
        }
#pragma unroll
        for (int k = 0; k < 16; k++) {
            float a[8], b[4];
            *(float4*)(a)     = *(float4*)&As[buf][k][r0];
            *(float4*)(a + 4) = *(float4*)&As[buf][k][r0 + 4];
            *(float4*)(b)     = *(float4*)&Bs[buf][k][c0];
#pragma unroll
            for (int i = 0; i < 8; i++)
#pragma unroll
                for (int j = 0; j < 4; j++) acc[i][j] += a[i] * b[j];
        }
        if (kc + 16 < 128) {
            *(float4*)&As[buf ^ 1][ka][ra4 * 4] = pa;
#pragma unroll
            for (int q = 0; q < 2; q++) {
                int e = tid + q * 256;
                int kk = e >> 5, c4 = e & 31;
                float4 v;
                if (t == 0)
                    v = make_float4(ph[q].x + pm[q].x, ph[q].y + pm[q].y,
                                    ph[q].z + pm[q].z, ph[q].w + pm[q].w);
                else
                    v = make_float4(ph[q].x - pm[q].x, ph[q].y - pm[q].y,
                                    ph[q].z - pm[q].z, ph[q].w - pm[q].w);
                *(float4*)&Bs[buf ^ 1][kk][c4 * 4] = v;
            }
        }
        __syncthreads();
        buf ^= 1;
    }
    if (t == 0) {
#pragma unroll
        for (int r = 0; r < 8; r++) {
            float sign = ((r0 + r) & 1) ? -1.0f : 1.0f;
#pragma unroll
            for (int j = 0; j < 4; j++) acc[r][j] += sign * xs[c0 + j];
        }
    }
    float* C = g_C + (size_t)n * 524288 + (size_t)(t * 64) * 4096 + cb;
#pragma unroll
    for (int i = 0; i < 8; i++) {
        int row = r0 + i;
        *(float4*)(C + (size_t)row * 4096 + c0) =
            make_float4(acc[i][0], acc[i][1], acc[i][2], acc[i][3]);
    }
}

// ---------------- S3: complex recombine + mode channel mix, scale 1/65536 ----------------
__global__ void __launch_bounds__(256) k_c(const float* __restrict__ w0,
                                           const float* __restrict__ w1) {
    __shared__ float Wre[64][64], Wim[64][64];
    __shared__ float Xre[8][64], Xim[8][64];
    int tid = threadIdx.x;
    int ky = blockIdx.x & 31, k = blockIdx.x >> 5;
    const float* W = (k < 32) ? (w0 + (size_t)(k * 32 + ky) * 4096 * 2)
                              : (w1 + (size_t)((k - 32) * 32 + ky) * 4096 * 2);
#pragma unroll
    for (int q = 0; q < 16; q++) {
        int e = tid + q * 256;
        float2 v = *(const float2*)(W + (size_t)e * 2);
        Wre[e >> 6][e & 63] = v.x;
        Wim[e >> 6][e & 63] = v.y;
    }
#pragma unroll
    for (int q = 0; q < 2; q++) {
        int e = tid + q * 256;
        int n = e >> 6, i = e & 63;
        const float* Cn = g_C + (size_t)n * 524288;
        float cc0 = Cn[(size_t)k * 4096 + ky * 64 + i];
        float cc1 = Cn[(size_t)k * 4096 + 2048 + ky * 64 + i];
        float cs0 = Cn[(size_t)(64 + k) * 4096 + ky * 64 + i];
        float cs1 = Cn[(size_t)(64 + k) * 4096 + 2048 + ky * 64 + i];
        Xre[n][i] = cc0 + cs1;
        Xim[n][i] = cc1 - cs0;
    }
    __syncthreads();
    const float sc = 1.0f / 65536.0f;
#pragma unroll
    for (int q = 0; q < 2; q++) {
        int e = tid + q * 256;
        int n = e >> 6, o = e & 63;
        float fre = 0.0f, fim = 0.0f;
#pragma unroll 8
        for (int i = 0; i < 64; i++) {
            float xr = Xre[n][i], xi = Xim[n][i];
            float wr = Wre[i][o], wi = Wim[i][o];
            fre += xr * wr - xi * wi;
            fim += xr * wi + xi * wr;
        }
        g_F[((size_t)(n * 128 + 2 * k) * 32 + ky) * 64 + o]     = fre * sc;
        g_F[((size_t)(n * 128 + 2 * k + 1) * 32 + ky) * 64 + o] = fim * sc;
    }
}

// ---------------- S4: per n: G[512 hp][2048] = T4[512][128] @ F[n], double-buffered ----------------
__global__ void __launch_bounds__(256, 2) k_s4() {
    __shared__ float As[2][16][132];
    __shared__ float Bs[2][16][128];
    int tid = threadIdx.x;
    int colbase = blockIdx.x * 128;
    int m0 = blockIdx.y * 128;
    int n = blockIdx.z;
    const float* B = g_F + (size_t)n * 128 * 2048;
    float acc[8][8] = {};
    int r0 = (tid >> 4) * 8, c0 = (tid & 15) * 8;

    float4 pa[2], pb[2];
#pragma unroll
    for (int q = 0; q < 2; q++) {
        int e = tid + q * 256;
        int kk = e >> 5, m4 = e & 31;
        pa[q] = *(const float4*)(g_T4T + (size_t)kk * 512 + m0 + m4 * 4);
        pb[q] = *(const float4*)(B + (size_t)kk * 2048 + colbase + m4 * 4);
    }
#pragma unroll
    for (int q = 0; q < 2; q++) {
        int e = tid + q * 256;
        int kk = e >> 5, m4 = e & 31;
        *(float4*)&As[0][kk][m4 * 4] = pa[q];
        *(float4*)&Bs[0][kk][m4 * 4] = pb[q];
    }
    __syncthreads();
    int buf = 0;
    for (int kc = 0; kc < 128; kc += 16) {
        if (kc + 16 < 128) {
#pragma unroll
            for (int q = 0; q < 2; q++) {
                int e = tid + q * 256;
                int kk = e >> 5, m4 = e & 31;
                pa[q] = *(const float4*)(g_T4T + (size_t)(kc + 16 + kk) * 512 + m0 + m4 * 4);
                pb[q] = *(const float4*)(B + (size_t)(kc + 16 + kk) * 2048 + colbase + m4 * 4);
            }
        }
#pragma unroll
        for (int k = 0; k < 16; k++) {
            float a[8], b[8];
            *(float4*)(a)     = *(float4*)&As[buf][k][r0];
            *(float4*)(a + 4) = *(float4*)&As[buf][k][r0 + 4];
            *(float4*)(b)     = *(float4*)&Bs[buf][k][c0];
            *(float4*)(b + 4) = *(float4*)&Bs[buf][k][c0 + 4];
#pragma unroll
            for (int i = 0; i < 8; i++)
#pragma unroll
                for (int j = 0; j < 8; j++) acc[i][j] += a[i] * b[j];
        }
        if (kc + 16 < 128) {
#pragma unroll
            for (int q = 0; q < 2; q++) {
                int e = tid + q * 256;
                int kk = e >> 5, m4 = e & 31;
                *(float4*)&As[buf ^ 1][kk][m4 * 4] = pa[q];
                *(float4*)&Bs[buf ^ 1][kk][m4 * 4] = pb[q];
            }
        }
        __syncthreads();
        buf ^= 1;
    }
    float* C = g_G + (size_t)n * 512 * 2048 + colbase;
#pragma unroll
    for (int i = 0; i < 8; i++) {
        int row = m0 + r0 + i;
        *(float4*)(C + (size_t)row * 2048 + c0)     = make_float4(acc[i][0], acc[i][1], acc[i][2], acc[i][3]);
        *(float4*)(C + (size_t)row * 2048 + c0 + 4) = make_float4(acc[i][4], acc[i][5], acc[i][6], acc[i][7]);
    }
}

// ---------------- S5 (fused with residual), w-half split, packed f32x2 mainloop ----------------
__global__ void __launch_bounds__(256) k_s5(const float* __restrict__ x,
                                            const float* __restrict__ rw,
                                            const float* __restrict__ rb,
                                            float* __restrict__ out) {
    extern __shared__ float sm[];
    float(*As)[132] = (float(*)[132])sm;              // [64 k][128 w(+pad)]
    float(*Bs)[68]  = (float(*)[68])(sm + 64 * 132);  // [64 k][64 o(+pad)]
    float* bb = sm + 64 * 132 + 64 * 68;
    int tid = threadIdx.x;
    int wh = blockIdx.x & 1;
    int h  = (blockIdx.x >> 1) & 255;
    int n  = blockIdx.x >> 9;
    int w0base = wh * 128;
    int r0 = (tid >> 4) * 8, c0 = (tid & 15) * 4;
    u64 acc2[4][4];                  // rows packed in pairs: acc2[i2][j] = (row r0+2i2, row r0+2i2+1)
#pragma unroll
    for (int i = 0; i < 4; i++)
#pragma unroll
        for (int j = 0; j < 4; j++) acc2[i][j] = 0ull;

    // ----- pass 1: spectral  As = T5t[k][w-half], Bs = G[kyp][o] -----
#pragma unroll
    for (int q = 0; q < 8; q++) {
        int e = tid + q * 256;
        int k = e >> 5, w4 = e & 31;
        *(float4*)&As[k][w4 * 4] = *(const float4*)(g_T5t + k * 256 + w0base + w4 * 4);
    }
    const float* G = g_G + (size_t)(n * 256 + h) * 4096;
#pragma unroll
    for (int q = 0; q < 4; q++) {
        int e4 = tid + q * 256;
        int p = e4 >> 9, ky = (e4 >> 4) & 31, j = e4 & 15;
        float4 v = *(const float4*)(G + p * 2048 + ky * 64 + j * 4);
        *(float4*)&Bs[2 * ky + p][j * 4] = v;
    }
    if (tid < 64) bb[tid] = rb[tid];
    __syncthreads();
#pragma unroll 8
    for (int k = 0; k < 64; k++) {
        u64 a2[4];
        *(ulonglong2*)(a2)     = *(ulonglong2*)&As[k][r0];      // row pairs (r0,r0+1),(r0+2,r0+3)
        *(ulonglong2*)(a2 + 2) = *(ulonglong2*)&As[k][r0 + 4];
        float b[4];
        *(float4*)b = *(float4*)&Bs[k][c0];
        u64 b2[4];
#pragma unroll
        for (int j = 0; j < 4; j++)
            asm("mov.b64 %0, {%1, %1};" : "=l"(b2[j]) : "f"(b[j]));
#pragma unroll
        for (int i = 0; i < 4; i++)
#pragma unroll
            for (int j = 0; j < 4; j++)
                asm("fma.rn.f32x2 %0, %1, %2, %0;" : "+l"(acc2[i][j]) : "l"(a2[i]), "l"(b2[j]));
    }
    __syncthreads();

    // ----- pass 2: residual  As = x[n,h]^T [i][w-half], Bs = rw [i][o] -----
    const float* xb = x + (size_t)(n * 256 + h) * 16384 + (size_t)w0base * 64;
#pragma unroll
    for (int q = 0; q < 8; q++) {
        int f4 = tid + q * 256;
        int w = f4 >> 4, j = f4 & 15;
        float4 v = *(const float4*)(xb + w * 64 + j * 4);
        As[j * 4 + 0][w] = v.x; As[j * 4 + 1][w] = v.y;
        As[j * 4 + 2][w] = v.z; As[j * 4 + 3][w] = v.w;
    }
#pragma unroll
    for (int q = 0; q < 4; q++) {
        int f4 = tid + q * 256;
        int k = f4 >> 4, j = f4 & 15;
        *(float4*)&Bs[k][j * 4] = *(const float4*)(rw + k * 64 + j * 4);
    }
    __syncthreads();
#pragma unroll 8
    for (int k = 0; k < 64; k++) {
        u64 a2[4];
        *(ulonglong2*)(a2)     = *(ulonglong2*)&As[k][r0];
        *(ulonglong2*)(a2 + 2) = *(ulonglong2*)&As[k][r0 + 4];
        float b[4];
        *(float4*)b = *(float4*)&Bs[k][c0];
        u64 b2[4];
#pragma unroll
        for (int j = 0; j < 4; j++)
            asm("mov.b64 %0, {%1, %1};" : "=l"(b2[j]) : "f"(b[j]));
#pragma unroll
        for (int i = 0; i < 4; i++)
#pragma unroll
            for (int j = 0; j < 4; j++)
                asm("fma.rn.f32x2 %0, %1, %2, %0;" : "+l"(acc2[i][j]) : "l"(a2[i]), "l"(b2[j]));
    }

    // ----- epilogue: unpack, bias + silu, store -----
    float* ob = out + (size_t)(n * 256 + h) * 16384 + (size_t)w0base * 64;
#pragma unroll
    for (int i = 0; i < 4; i++) {
        float lo[4], hi[4];
#pragma unroll
        for (int j = 0; j < 4; j++)
            asm("mov.b64 {%0, %1}, %2;" : "=f"(lo[j]), "=f"(hi[j]) : "l"(acc2[i][j]));
        int wA = r0 + 2 * i, wB = wA + 1;
        float4 oA, oB;
        oA.x = silu_f(lo[0] + bb[c0 + 0]); oA.y = silu_f(lo[1] + bb[c0 + 1]);
        oA.z = silu_f(lo[2] + bb[c0 + 2]); oA.w = silu_f(lo[3] + bb[c0 + 3]);
        oB.x = silu_f(hi[0] + bb[c0 + 0]); oB.y = silu_f(hi[1] + bb[c0 + 1]);
        oB.z = silu_f(hi[2] + bb[c0 + 2]); oB.w = silu_f(hi[3] + bb[c0 + 3]);
        *(float4*)(ob + (size_t)wA * 64 + c0) = oA;
        *(float4*)(ob + (size_t)wB * 64 + c0) = oB;
    }
}

// ---------------- launch ----------------
extern "C" void kernel_launch(void* const* d_in, const int* in_sizes, int n_in,
                              void* d_out, int out_size) {
    const float* x  = (const float*)d_in[0];
    const float* w0 = (const float*)d_in[1];
    const float* w1 = (const float*)d_in[2];
    const float* rw = (const float*)d_in[3];
    const float* rb = (const float*)d_in[4];
    float* out = (float*)d_out;

    const int SMEM_S5 = (64 * 132 + 64 * 68 + 64) * 4;   // 51456 bytes
    cudaFuncSetAttribute(k_s5, cudaFuncAttributeMaxDynamicSharedMemorySize, SMEM_S5);

    k_init<<<64, 256>>>();
    dim3 ga(32, 2, 8);                 // hg, type, n
    k_a<<<ga, 256>>>(x);
    dim3 gb(32, 8, 2);                 // colblock, n, type
    k_b<<<gb, 256>>>();
    k_c<<<2048, 256>>>(w0, w1);
    dim3 g4(16, 4, 8);
    k_s4<<<g4, 256>>>();
    k_s5<<<4096, 256, SMEM_S5>>>(x, rw, rb, out);   // 8 n * 256 h * 2 w-halves
}

// round 17
// speedup vs baseline: 1.1944x; 1.0335x over previous
#include <cuda_runtime.h>
#include <math.h>

typedef unsigned long long u64;

// Problem constants: N=8, R=256, IN=64, OUT=64, MODE=32
// kx mode list (64): k<32 -> kx=k ; k>=32 -> kx=192+k

// ---------------- device scratch ----------------
__device__ float g_TA[128 * 64];      // fwd w-DFT folded: [w][r]  r<32: cos, r>=32: -sin
__device__ float g_TB[128 * 128];     // fwd h-DFT folded: [h][c]  c<64: cos, c>=64: +sin
__device__ float g_T4T[128 * 512];    // inv h-DFT, transposed: [kxp][hp]
__device__ float g_T5t[64 * 256];     // inv w-DFT, transposed: [kyp][w]
__device__ float g_Xw[(size_t)8 * 256 * 4096];  // [n][h][p*2048+ky*64+i]
__device__ float g_C [(size_t)8 * 128 * 4096];  // [n][m(cos|sin)][p*2048+ky*64+i]
__device__ float g_F [(size_t)8 * 128 * 32 * 64]; // [n][kxp][ky][o]
__device__ float g_G [(size_t)8 * 512 * 2048];    // [n][hp][ky*64+o]

__device__ __forceinline__ float silu_f(float t) {
    return t / (1.0f + __expf(-t));
}
__device__ __forceinline__ u64 dup_f32x2(float v) {
    u64 r;
    asm("mov.b64 %0, {%1, %1};" : "=l"(r) : "f"(v));
    return r;
}
#define FMA2(acc, a, b) asm("fma.rn.f32x2 %0, %1, %2, %0;" : "+l"(acc) : "l"(a), "l"(b))

// ---------------- twiddle init ----------------
__global__ void k_init() {
    int t = blockIdx.x * blockDim.x + threadIdx.x;   // 16384 threads
    if (t < 8192) {
        int w = t >> 6, rr = t & 63;
        int ty = rr >> 5, ky = rr & 31;
        float s, c;
        sincospif((float)((ky * w) & 255) * (1.0f / 128.0f), &s, &c);
        g_TA[w * 64 + rr] = ty ? -s : c;
    }
    {
        int h = t >> 7, cc = t & 127;
        int ty = cc >> 6, k = cc & 63;
        int kx = (k < 32) ? k : 192 + k;
        float s, c;
        sincospif((float)((kx * h) & 255) * (1.0f / 128.0f), &s, &c);
        g_TB[h * 128 + cc] = ty ? s : c;
    }
    {
        int h = t >> 6, k = t & 63;
        int kx = (k < 32) ? k : 192 + k;
        float s, c;
        sincospif((float)((kx * h) & 255) * (1.0f / 128.0f), &s, &c);
        g_T4T[(2 * k)     * 512 + 2 * h]     = c;
        g_T4T[(2 * k + 1) * 512 + 2 * h]     = -s;
        g_T4T[(2 * k)     * 512 + 2 * h + 1] = s;
        g_T4T[(2 * k + 1) * 512 + 2 * h + 1] = c;
    }
    {
        int r = t >> 8, w = t & 255;
        int ky = r >> 1, p = r & 1;
        float s, c;
        sincospif((float)((ky * w) & 255) * (1.0f / 128.0f), &s, &c);
        float f = (ky == 0) ? 1.0f : 2.0f;
        g_T5t[r * 256 + w] = p ? -f * s : f * c;
    }
}

// ---------------- Stage A (folded): per (n, 8h, type t), f32x2 mainloop ----------------
__global__ void __launch_bounds__(256) k_a(const float* __restrict__ x) {
    __shared__ __align__(16) float As[16][36];     // [kk][32 r]
    __shared__ __align__(16) float Bs[16][512];    // [kk][8h x 64i]
    __shared__ __align__(16) float xs[512];        // x[*, w=128, *] for correction (t=0)
    int tid = threadIdx.x;
    int hg = blockIdx.x, t = blockIdx.y, n = blockIdx.z;
    int h0 = hg * 8;
    const float* xb = x + (size_t)n * 4194304 + (size_t)h0 * 16384;
    if (tid < 128) {
        int hl = tid >> 4, i4 = tid & 15;
        *(float4*)&xs[hl * 64 + i4 * 4] = *(const float4*)(xb + hl * 16384 + 128 * 64 + i4 * 4);
    }
    u64 acc2[4][8];                  // [row i][col-pair j2]: j2 covers 16 cols as 8 pairs
#pragma unroll
    for (int i = 0; i < 4; i++)
#pragma unroll
        for (int j = 0; j < 8; j++) acc2[i][j] = 0ull;
    int r0 = (tid >> 5) * 4;
    int cg0 = (tid & 31) * 4;

    for (int kc = 0; kc < 128; kc += 16) {
        if (tid < 128) {
            int kk = tid >> 3, r4 = tid & 7;
            *(float4*)&As[kk][r4 * 4] = *(const float4*)(g_TA + (kc + kk) * 64 + t * 32 + r4 * 4);
        }
#pragma unroll
        for (int q = 0; q < 8; q++) {
            int e = tid + q * 256;
            int kk = e >> 7, c4 = e & 127;
            int hl = c4 >> 4, i4 = c4 & 15;
            int w = kc + kk;
            int m = (256 - w) & 255;
            const float* base = xb + hl * 16384;
            float4 vw = *(const float4*)(base + (size_t)w * 64 + i4 * 4);
            float4 vm = *(const float4*)(base + (size_t)m * 64 + i4 * 4);
            float4 v;
            if (t == 0) {
                v = w ? make_float4(vw.x + vm.x, vw.y + vm.y, vw.z + vm.z, vw.w + vm.w) : vw;
            } else {
                v = w ? make_float4(vw.x - vm.x, vw.y - vm.y, vw.z - vm.z, vw.w - vm.w)
                      : make_float4(0.f, 0.f, 0.f, 0.f);
            }
            *(float4*)&Bs[kk][c4 * 4] = v;
        }
        __syncthreads();
#pragma unroll
        for (int k = 0; k < 16; k++) {
            float a[4];
            *(float4*)a = *(float4*)&As[k][r0];
            u64 a2[4];
#pragma unroll
            for (int i = 0; i < 4; i++) a2[i] = dup_f32x2(a[i]);
            u64 b2[8];
#pragma unroll
            for (int g = 0; g < 4; g++)
                *(ulonglong2*)(b2 + g * 2) = *(ulonglong2*)&Bs[k][cg0 + g * 128];
#pragma unroll
            for (int i = 0; i < 4; i++)
#pragma unroll
                for (int j = 0; j < 8; j++) FMA2(acc2[i][j], a2[i], b2[j]);
        }
        __syncthreads();
    }
    // unpack
    float acc[4][16];
#pragma unroll
    for (int i = 0; i < 4; i++)
#pragma unroll
        for (int j = 0; j < 8; j++)
            asm("mov.b64 {%0, %1}, %2;" : "=f"(acc[i][2 * j]), "=f"(acc[i][2 * j + 1]) : "l"(acc2[i][j]));
    if (t == 0) {
#pragma unroll
        for (int r = 0; r < 4; r++) {
            float sign = ((r0 + r) & 1) ? -1.0f : 1.0f;
#pragma unroll
            for (int g = 0; g < 4; g++) {
                int cg = cg0 + g * 128;
#pragma unroll
                for (int j = 0; j < 4; j++) acc[r][g * 4 + j] += sign * xs[cg + j];
            }
        }
    }
#pragma unroll
    for (int r = 0; r < 4; r++) {
        int ky = r0 + r;
#pragma unroll
        for (int g = 0; g < 4; g++) {
            int cg = cg0 + g * 128;
            int hl = cg >> 6, ib = cg & 63;
            float* O = g_Xw + (size_t)n * 1048576 + (size_t)(h0 + hl) * 4096 + t * 2048 + ky * 64 + ib;
            *(float4*)O = make_float4(acc[r][g * 4 + 0], acc[r][g * 4 + 1],
                                      acc[r][g * 4 + 2], acc[r][g * 4 + 3]);
        }
    }
}

// ---------------- Stage B (folded): per (colblock, n, type t), f32x2 mainloop ----------------
__global__ void __launch_bounds__(256, 2) k_b() {
    __shared__ __align__(16) float As[2][16][68];
    __shared__ __align__(16) float Bs[2][16][128];
    __shared__ __align__(16) float xs[128];
    int tid = threadIdx.x;
    int cb = blockIdx.x * 128;
    int n = blockIdx.y, t = blockIdx.z;
    const float* B = g_Xw + (size_t)n * 1048576;
    if (tid < 32)
        *(float4*)&xs[tid * 4] = *(const float4*)(B + (size_t)128 * 4096 + cb + tid * 4);
    u64 acc2[4][4];                 // [row-pair i2][col j]
#pragma unroll
    for (int i = 0; i < 4; i++)
#pragma unroll
        for (int j = 0; j < 4; j++) acc2[i][j] = 0ull;
    int r0 = (tid >> 5) * 8, c0 = (tid & 31) * 4;
    int ka = tid >> 4, ra4 = tid & 15;

    float4 pa;
    float4 ph[2], pm[2];
    pa = *(const float4*)(g_TB + ka * 128 + t * 64 + ra4 * 4);
#pragma unroll
    for (int q = 0; q < 2; q++) {
        int e = tid + q * 256;
        int kk = e >> 5, c4 = e & 31;
        int m = (256 - kk) & 255;
        ph[q] = *(const float4*)(B + (size_t)kk * 4096 + cb + c4 * 4);
        pm[q] = *(const float4*)(B + (size_t)m * 4096 + cb + c4 * 4);
    }
    {
        *(float4*)&As[0][ka][ra4 * 4] = pa;
#pragma unroll
        for (int q = 0; q < 2; q++) {
            int e = tid + q * 256;
            int kk = e >> 5, c4 = e & 31;
            float4 v;
            if (t == 0)
                v = kk ? make_float4(ph[q].x + pm[q].x, ph[q].y + pm[q].y,
                                     ph[q].z + pm[q].z, ph[q].w + pm[q].w) : ph[q];
            else
                v = kk ? make_float4(ph[q].x - pm[q].x, ph[q].y - pm[q].y,
                                     ph[q].z - pm[q].z, ph[q].w - pm[q].w)
                       : make_float4(0.f, 0.f, 0.f, 0.f);
            *(float4*)&Bs[0][kk][c4 * 4] = v;
        }
    }
    __syncthreads();
    int buf = 0;
    for (int kc = 0; kc < 128; kc += 16) {
        if (kc + 16 < 128) {
            pa = *(const float4*)(g_TB + (kc + 16 + ka) * 128 + t * 64 + ra4 * 4);
#pragma unroll
            for (int q = 0; q < 2; q++) {
                int e = tid + q * 256;
                int kk = e >> 5, c4 = e & 31;
                int h = kc + 16 + kk;
                int m = (256 - h) & 255;
                ph[q] = *(const float4*)(B + (size_t)h * 4096 + cb + c4 * 4);
                pm[q] = *(const float4*)(B + (size_t)m * 4096 + cb + c4 * 4);
            }
        }
#pragma unroll
        for (int k = 0; k < 16; k++) {
            u64 a2[4];
            *(ulonglong2*)(a2)     = *(ulonglong2*)&As[buf][k][r0];
            *(ulonglong2*)(a2 + 2) = *(ulonglong2*)&As[buf][k][r0 + 4];
            float b[4];
            *(float4*)b = *(float4*)&Bs[buf][k][c0];
            u64 b2[4];
#pragma unroll
            for (int j = 0; j < 4; j++) b2[j] = dup_f32x2(b[j]);
#pragma unroll
            for (int i = 0; i < 4; i++)
#pragma unroll
                for (int j = 0; j < 4; j++) FMA2(acc2[i][j], a2[i], b2[j]);
        }
        if (kc + 16 < 128) {
            *(float4*)&As[buf ^ 1][ka][ra4 * 4] = pa;
#pragma unroll
            for (int q = 0; q < 2; q++) {
                int e = tid + q * 256;
                int kk = e >> 5, c4 = e & 31;
                float4 v;
                if (t == 0)
                    v = make_float4(ph[q].x + pm[q].x, ph[q].y + pm[q].y,
                                    ph[q].z + pm[q].z, ph[q].w + pm[q].w);
                else
                    v = make_float4(ph[q].x - pm[q].x, ph[q].y - pm[q].y,
                                    ph[q].z - pm[q].z, ph[q].w - pm[q].w);
                *(float4*)&Bs[buf ^ 1][kk][c4 * 4] = v;
            }
        }
        __syncthreads();
        buf ^= 1;
    }
    // unpack: acc2[i2][j] -> rows r0+2i2, r0+2i2+1
    float acc[8][4];
#pragma unroll
    for (int i = 0; i < 4; i++)
#pragma unroll
        for (int j = 0; j < 4; j++)
            asm("mov.b64 {%0, %1}, %2;" : "=f"(acc[2 * i][j]), "=f"(acc[2 * i + 1][j]) : "l"(acc2[i][j]));
    if (t == 0) {
#pragma unroll
        for (int r = 0; r < 8; r++) {
            float sign = ((r0 + r) & 1) ? -1.0f : 1.0f;
#pragma unroll
            for (int j = 0; j < 4; j++) acc[r][j] += sign * xs[c0 + j];
        }
    }
    float* C = g_C + (size_t)n * 524288 + (size_t)(t * 64) * 4096 + cb;
#pragma unroll
    for (int i = 0; i < 8; i++) {
        int row = r0 + i;
        *(float4*)(C + (size_t)row * 4096 + c0) =
            make_float4(acc[i][0], acc[i][1], acc[i][2], acc[i][3]);
    }
}

// ---------------- S3: complex recombine + mode channel mix, scale 1/65536 ----------------
__global__ void __launch_bounds__(256) k_c(const float* __restrict__ w0,
                                           const float* __restrict__ w1) {
    __shared__ float Wre[64][64], Wim[64][64];
    __shared__ float Xre[8][64], Xim[8][64];
    int tid = threadIdx.x;
    int ky = blockIdx.x & 31, k = blockIdx.x >> 5;
    const float* W = (k < 32) ? (w0 + (size_t)(k * 32 + ky) * 4096 * 2)
                              : (w1 + (size_t)((k - 32) * 32 + ky) * 4096 * 2);
#pragma unroll
    for (int q = 0; q < 16; q++) {
        int e = tid + q * 256;
        float2 v = *(const float2*)(W + (size_t)e * 2);
        Wre[e >> 6][e & 63] = v.x;
        Wim[e >> 6][e & 63] = v.y;
    }
#pragma unroll
    for (int q = 0; q < 2; q++) {
        int e = tid + q * 256;
        int n = e >> 6, i = e & 63;
        const float* Cn = g_C + (size_t)n * 524288;
        float cc0 = Cn[(size_t)k * 4096 + ky * 64 + i];
        float cc1 = Cn[(size_t)k * 4096 + 2048 + ky * 64 + i];
        float cs0 = Cn[(size_t)(64 + k) * 4096 + ky * 64 + i];
        float cs1 = Cn[(size_t)(64 + k) * 4096 + 2048 + ky * 64 + i];
        Xre[n][i] = cc0 + cs1;
        Xim[n][i] = cc1 - cs0;
    }
    __syncthreads();
    const float sc = 1.0f / 65536.0f;
#pragma unroll
    for (int q = 0; q < 2; q++) {
        int e = tid + q * 256;
        int n = e >> 6, o = e & 63;
        float fre = 0.0f, fim = 0.0f;
#pragma unroll 8
        for (int i = 0; i < 64; i++) {
            float xr = Xre[n][i], xi = Xim[n][i];
            float wr = Wre[i][o], wi = Wim[i][o];
            fre += xr * wr - xi * wi;
            fim += xr * wi + xi * wr;
        }
        g_F[((size_t)(n * 128 + 2 * k) * 32 + ky) * 64 + o]     = fre * sc;
        g_F[((size_t)(n * 128 + 2 * k + 1) * 32 + ky) * 64 + o] = fim * sc;
    }
}

// ---------------- S4: per n: G = T4 @ F, double-buffered, f32x2 mainloop ----------------
__global__ void __launch_bounds__(256, 2) k_s4() {
    __shared__ __align__(16) float As[2][16][132];
    __shared__ __align__(16) float Bs[2][16][128];
    int tid = threadIdx.x;
    int colbase = blockIdx.x * 128;
    int m0 = blockIdx.y * 128;
    int n = blockIdx.z;
    const float* B = g_F + (size_t)n * 128 * 2048;
    u64 acc2[8][4];                 // [row i][col-pair j2]
#pragma unroll
    for (int i = 0; i < 8; i++)
#pragma unroll
        for (int j = 0; j < 4; j++) acc2[i][j] = 0ull;
    int r0 = (tid >> 4) * 8, c0 = (tid & 15) * 8;

    float4 pa[2], pb[2];
#pragma unroll
    for (int q = 0; q < 2; q++) {
        int e = tid + q * 256;
        int kk = e >> 5, m4 = e & 31;
        pa[q] = *(const float4*)(g_T4T + (size_t)kk * 512 + m0 + m4 * 4);
        pb[q] = *(const float4*)(B + (size_t)kk * 2048 + colbase + m4 * 4);
    }
#pragma unroll
    for (int q = 0; q < 2; q++) {
        int e = tid + q * 256;
        int kk = e >> 5, m4 = e & 31;
        *(float4*)&As[0][kk][m4 * 4] = pa[q];
        *(float4*)&Bs[0][kk][m4 * 4] = pb[q];
    }
    __syncthreads();
    int buf = 0;
    for (int kc = 0; kc < 128; kc += 16) {
        if (kc + 16 < 128) {
#pragma unroll
            for (int q = 0; q < 2; q++) {
                int e = tid + q * 256;
                int kk = e >> 5, m4 = e & 31;
                pa[q] = *(const float4*)(g_T4T + (size_t)(kc + 16 + kk) * 512 + m0 + m4 * 4);
                pb[q] = *(const float4*)(B + (size_t)(kc + 16 + kk) * 2048 + colbase + m4 * 4);
            }
        }
#pragma unroll
        for (int k = 0; k < 16; k++) {
            float a[8];
            *(float4*)(a)     = *(float4*)&As[buf][k][r0];
            *(float4*)(a + 4) = *(float4*)&As[buf][k][r0 + 4];
            u64 a2[8];
#pragma unroll
            for (int i = 0; i < 8; i++) a2[i] = dup_f32x2(a[i]);
            u64 b2[4];
            *(ulonglong2*)(b2)     = *(ulonglong2*)&Bs[buf][k][c0];
            *(ulonglong2*)(b2 + 2) = *(ulonglong2*)&Bs[buf][k][c0 + 4];
#pragma unroll
            for (int i = 0; i < 8; i++)
#pragma unroll
                for (int j = 0; j < 4; j++) FMA2(acc2[i][j], a2[i], b2[j]);
        }
        if (kc + 16 < 128) {
#pragma unroll
            for (int q = 0; q < 2; q++) {
                int e = tid + q * 256;
                int kk = e >> 5, m4 = e & 31;
                *(float4*)&As[buf ^ 1][kk][m4 * 4] = pa[q];
                *(float4*)&Bs[buf ^ 1][kk][m4 * 4] = pb[q];
            }
        }
        __syncthreads();
        buf ^= 1;
    }
    float* C = g_G + (size_t)n * 512 * 2048 + colbase;
#pragma unroll
    for (int i = 0; i < 8; i++) {
        int row = m0 + r0 + i;
        float v[8];
#pragma unroll
        for (int j = 0; j < 4; j++)
            asm("mov.b64 {%0, %1}, %2;" : "=f"(v[2 * j]), "=f"(v[2 * j + 1]) : "l"(acc2[i][j]));
        *(float4*)(C + (size_t)row * 2048 + c0)     = make_float4(v[0], v[1], v[2], v[3]);
        *(float4*)(C + (size_t)row * 2048 + c0 + 4) = make_float4(v[4], v[5], v[6], v[7]);
    }
}

// ---------------- S5 (fused with residual), w-half split, packed f32x2 mainloop ----------------
__global__ void __launch_bounds__(256) k_s5(const float* __restrict__ x,
                                            const float* __restrict__ rw,
                                            const float* __restrict__ rb,
                                            float* __restrict__ out) {
    extern __shared__ float sm[];
    float(*As)[132] = (float(*)[132])sm;              // [64 k][128 w(+pad)]
    float(*Bs)[68]  = (float(*)[68])(sm + 64 * 132);  // [64 k][64 o(+pad)]
    float* bb = sm + 64 * 132 + 64 * 68;
    int tid = threadIdx.x;
    int wh = blockIdx.x & 1;
    int h  = (blockIdx.x >> 1) & 255;
    int n  = blockIdx.x >> 9;
    int w0base = wh * 128;
    int r0 = (tid >> 4) * 8, c0 = (tid & 15) * 4;
    u64 acc2[4][4];                  // rows packed in pairs
#pragma unroll
    for (int i = 0; i < 4; i++)
#pragma unroll
        for (int j = 0; j < 4; j++) acc2[i][j] = 0ull;

    // ----- pass 1: spectral  As = T5t[k][w-half], Bs = G[kyp][o] -----
#pragma unroll
    for (int q = 0; q < 8; q++) {
        int e = tid + q * 256;
        int k = e >> 5, w4 = e & 31;
        *(float4*)&As[k][w4 * 4] = *(const float4*)(g_T5t + k * 256 + w0base + w4 * 4);
    }
    const float* G = g_G + (size_t)(n * 256 + h) * 4096;
#pragma unroll
    for (int q = 0; q < 4; q++) {
        int e4 = tid + q * 256;
        int p = e4 >> 9, ky = (e4 >> 4) & 31, j = e4 & 15;
        float4 v = *(const float4*)(G + p * 2048 + ky * 64 + j * 4);
        *(float4*)&Bs[2 * ky + p][j * 4] = v;
    }
    if (tid < 64) bb[tid] = rb[tid];
    __syncthreads();
#pragma unroll 8
    for (int k = 0; k < 64; k++) {
        u64 a2[4];
        *(ulonglong2*)(a2)     = *(ulonglong2*)&As[k][r0];
        *(ulonglong2*)(a2 + 2) = *(ulonglong2*)&As[k][r0 + 4];
        float b[4];
        *(float4*)b = *(float4*)&Bs[k][c0];
        u64 b2[4];
#pragma unroll
        for (int j = 0; j < 4; j++) b2[j] = dup_f32x2(b[j]);
#pragma unroll
        for (int i = 0; i < 4; i++)
#pragma unroll
            for (int j = 0; j < 4; j++) FMA2(acc2[i][j], a2[i], b2[j]);
    }
    __syncthreads();

    // ----- pass 2: residual  As = x[n,h]^T [i][w-half], Bs = rw [i][o] -----
    const float* xb = x + (size_t)(n * 256 + h) * 16384 + (size_t)w0base * 64;
#pragma unroll
    for (int q = 0; q < 8; q++) {
        int f4 = tid + q * 256;
        int w = f4 >> 4, j = f4 & 15;
        float4 v = *(const float4*)(xb + w * 64 + j * 4);
        As[j * 4 + 0][w] = v.x; As[j * 4 + 1][w] = v.y;
        As[j * 4 + 2][w] = v.z; As[j * 4 + 3][w] = v.w;
    }
#pragma unroll
    for (int q = 0; q < 4; q++) {
        int f4 = tid + q * 256;
        int k = f4 >> 4, j = f4 & 15;
        *(float4*)&Bs[k][j * 4] = *(const float4*)(rw + k * 64 + j * 4);
    }
    __syncthreads();
#pragma unroll 8
    for (int k = 0; k < 64; k++) {
        u64 a2[4];
        *(ulonglong2*)(a2)     = *(ulonglong2*)&As[k][r0];
        *(ulonglong2*)(a2 + 2) = *(ulonglong2*)&As[k][r0 + 4];
        float b[4];
        *(float4*)b = *(float4*)&Bs[k][c0];
        u64 b2[4];
#pragma unroll
        for (int j = 0; j < 4; j++) b2[j] = dup_f32x2(b[j]);
#pragma unroll
        for (int i = 0; i < 4; i++)
#pragma unroll
            for (int j = 0; j < 4; j++) FMA2(acc2[i][j], a2[i], b2[j]);
    }

    // ----- epilogue: unpack, bias + silu, store -----
    float* ob = out + (size_t)(n * 256 + h) * 16384 + (size_t)w0base * 64;
#pragma unroll
    for (int i = 0; i < 4; i++) {
        float lo[4], hi[4];
#pragma unroll
        for (int j = 0; j < 4; j++)
            asm("mov.b64 {%0, %1}, %2;" : "=f"(lo[j]), "=f"(hi[j]) : "l"(acc2[i][j]));
        int wA = r0 + 2 * i, wB = wA + 1;
        float4 oA, oB;
        oA.x = silu_f(lo[0] + bb[c0 + 0]); oA.y = silu_f(lo[1] + bb[c0 + 1]);
        oA.z = silu_f(lo[2] + bb[c0 + 2]); oA.w = silu_f(lo[3] + bb[c0 + 3]);
        oB.x = silu_f(hi[0] + bb[c0 + 0]); oB.y = silu_f(hi[1] + bb[c0 + 1]);
        oB.z = silu_f(hi[2] + bb[c0 + 2]); oB.w = silu_f(hi[3] + bb[c0 + 3]);
        *(float4*)(ob + (size_t)wA * 64 + c0) = oA;
        *(float4*)(ob + (size_t)wB * 64 + c0) = oB;
    }
}

// ---------------- launch ----------------
extern "C" void kernel_launch(void* const* d_in, const int* in_sizes, int n_in,
                              void* d_out, int out_size) {
    const float* x  = (const float*)d_in[0];
    const float* w0 = (const float*)d_in[1];
    const float* w1 = (const float*)d_in[2];
    const float* rw = (const float*)d_in[3];
    const float* rb = (const float*)d_in[4];
    float* out = (float*)d_out;

    const int SMEM_S5 = (64 * 132 + 64 * 68 + 64) * 4;   // 51456 bytes
    cudaFuncSetAttribute(k_s5, cudaFuncAttributeMaxDynamicSharedMemorySize, SMEM_S5);

    k_init<<<64, 256>>>();
    dim3 ga(32, 2, 8);                 // hg, type, n
    k_a<<<ga, 256>>>(x);
    dim3 gb(32, 8, 2);                 // colblock, n, type
    k_b<<<gb, 256>>>();
    k_c<<<2048, 256>>>(w0, w1);
    dim3 g4(16, 4, 8);
    k_s4<<<g4, 256>>>();
    k_s5<<<4096, 256, SMEM_S5>>>(x, rw, rb, out);   // 8 n * 256 h * 2 w-halves
}